// round 3
// baseline (speedup 1.0000x reference)
#include <cuda_runtime.h>
#include <math_constants.h>

// Problem constants
#define BB   4
#define TT   4096
#define DIN  1024
#define HH   16
#define DD   64
#define MM   (BB*TT)      // 16384 rows
#define NN   (HH*DD*2)    // 2048 gemm cols
#define HD   (HH*DD)      // 1024

// scan chunking
#define NCH  32
#define TC   (TT/NCH)     // 128

// GEMM tiling
#define Bb_M 128
#define Bb_N 64
#define BB_K 16
#define T_M  8
#define T_N  4

// ---------------- scratch (device globals; no allocation allowed) ----------------
__device__ float g_K[(size_t)MM * HD];     // 64 MB  k = kv[...,0], deinterleaved
__device__ float g_V[(size_t)MM * HD];     // 64 MB  v = kv[...,1]
__device__ float g_ST[(size_t)MM * HH];    // 1 MB   scores
__device__ float g_AggM[BB*HH*NCH];
__device__ float g_AggU[BB*HH*NCH];
__device__ float g_AggW[BB*HH*NCH*DD];
__device__ float g_PreM[BB*HH*NCH];
__device__ float g_PreU[BB*HH*NCH];
__device__ float g_PreW[BB*HH*NCH*DD];

// ---------------- zero output ----------------
__global__ void zero_kernel(float* __restrict__ out, int n) {
    int i = blockIdx.x * blockDim.x + threadIdx.x;
    if (i < n) out[i] = 0.0f;
}

// ---------------- GEMM: kv = relu(inputs @ kv_kernel), deinterleave to K/V ----------------
__global__ __launch_bounds__(256) void gemm_relu_kernel(
    const float* __restrict__ A,   // [MM, DIN]
    const float* __restrict__ W)   // [DIN, NN]
{
    __shared__ float As[BB_K][Bb_M];
    __shared__ float Bs[BB_K][Bb_N];

    const int tid = threadIdx.x;
    const int m0  = blockIdx.y * Bb_M;
    const int n0  = blockIdx.x * Bb_N;

    const int tx = tid & 15;   // 16 x TN=4 -> 64 cols
    const int ty = tid >> 4;   // 16 x TM=8 -> 128 rows

    // A load mapping: each thread 2x float4
    const int arow = tid >> 2;            // 0..63
    const int acol = (tid & 3) * 4;       // 0,4,8,12
    // B load mapping: each thread 1x float4
    const int brow = tid >> 4;            // 0..15
    const int bcol = (tid & 15) * 4;      // 0..60

    float acc[T_M][T_N];
#pragma unroll
    for (int i = 0; i < T_M; ++i)
#pragma unroll
        for (int j = 0; j < T_N; ++j) acc[i][j] = 0.0f;

    const float* Abase = A + (size_t)m0 * DIN;

    for (int k0 = 0; k0 < DIN; k0 += BB_K) {
        float4 a0 = *(const float4*)(Abase + (size_t)arow        * DIN + k0 + acol);
        float4 a1 = *(const float4*)(Abase + (size_t)(arow + 64) * DIN + k0 + acol);
        float4 b0 = *(const float4*)(W + (size_t)(k0 + brow) * NN + n0 + bcol);

        __syncthreads();   // finish reads of previous tile
        As[acol + 0][arow] = a0.x;
        As[acol + 1][arow] = a0.y;
        As[acol + 2][arow] = a0.z;
        As[acol + 3][arow] = a0.w;
        As[acol + 0][arow + 64] = a1.x;
        As[acol + 1][arow + 64] = a1.y;
        As[acol + 2][arow + 64] = a1.z;
        As[acol + 3][arow + 64] = a1.w;
        *(float4*)&Bs[brow][bcol] = b0;
        __syncthreads();

#pragma unroll
        for (int k = 0; k < BB_K; ++k) {
            float ar[T_M], br[T_N];
            float4 av0 = *(const float4*)&As[k][ty * T_M];
            float4 av1 = *(const float4*)&As[k][ty * T_M + 4];
            ar[0]=av0.x; ar[1]=av0.y; ar[2]=av0.z; ar[3]=av0.w;
            ar[4]=av1.x; ar[5]=av1.y; ar[6]=av1.z; ar[7]=av1.w;
            float4 bv = *(const float4*)&Bs[k][tx * T_N];
            br[0]=bv.x; br[1]=bv.y; br[2]=bv.z; br[3]=bv.w;
#pragma unroll
            for (int i = 0; i < T_M; ++i)
#pragma unroll
                for (int j = 0; j < T_N; ++j)
                    acc[i][j] = fmaf(ar[i], br[j], acc[i][j]);
        }
    }

    // epilogue: relu + deinterleave. thread cols = n0 + tx*4 + {0,1,2,3}
    // even -> K col (n)/2, odd -> V col (n)/2. c = (n0 + tx*4)/2 (even, float2-aligned)
    const int c = (n0 + tx * T_N) >> 1;
#pragma unroll
    for (int i = 0; i < T_M; ++i) {
        const size_t m = (size_t)(m0 + ty * T_M + i);
        float2 kv2_k = make_float2(fmaxf(acc[i][0], 0.0f), fmaxf(acc[i][2], 0.0f));
        float2 kv2_v = make_float2(fmaxf(acc[i][1], 0.0f), fmaxf(acc[i][3], 0.0f));
        *(float2*)(g_K + m * HD + c) = kv2_k;
        *(float2*)(g_V + m * HD + c) = kv2_v;
    }
}

// ---------------- st[b,t,h] = sum_d q[h,d] * K[row, h*64+d] ----------------
__global__ __launch_bounds__(256) void st_kernel(const float* __restrict__ q)
{
    const int gwarp = (blockIdx.x * blockDim.x + threadIdx.x) >> 5;
    const int lane  = threadIdx.x & 31;
    if (gwarp >= MM * HH) return;
    const int m = gwarp >> 4;      // row
    const int h = gwarp & 15;
    const float* krow = g_K + (size_t)m * HD + h * DD;
    const float* qrow = q + h * DD;
    float s = krow[lane] * qrow[lane] + krow[lane + 32] * qrow[lane + 32];
#pragma unroll
    for (int off = 16; off > 0; off >>= 1)
        s += __shfl_xor_sync(0xffffffffu, s, off);
    if (lane == 0) g_ST[(size_t)m * HH + h] = s;
}

// ---------------- scan combine step ----------------
__device__ __forceinline__ void scan_step(float& m, float& u, float& w, float s, float v)
{
    float mn = fmaxf(m, s);
    float sc = __expf(m - mn);   // exp(-inf) = 0 handles identity state
    float e  = __expf(s - mn);
    u = u * sc + e;
    w = w * sc + e * v;
    m = mn;
}

// ---------------- pass A: per-chunk aggregates ----------------
__global__ __launch_bounds__(64) void passA_kernel()
{
    const int chain = blockIdx.y;          // b*H + h
    const int chunk = blockIdx.x;
    const int d     = threadIdx.x;
    const int b = chain >> 4, h = chain & 15;

    float m = -CUDART_INF_F, u = 0.0f, w = 0.0f;
    const int t0 = chunk * TC;
#pragma unroll 4
    for (int t = t0; t < t0 + TC; ++t) {
        const size_t row = (size_t)b * TT + t;
        float s = g_ST[row * HH + h];
        float v = g_V[row * HD + h * DD + d];
        scan_step(m, u, w, s, v);
    }
    const int idx = chain * NCH + chunk;
    if (d == 0) { g_AggM[idx] = m; g_AggU[idx] = u; }
    g_AggW[idx * DD + d] = w;
}

// ---------------- pass B: exclusive prefix over chunks (serial, tiny) ----------------
__global__ __launch_bounds__(64) void passB_kernel()
{
    const int chain = blockIdx.x;
    const int d     = threadIdx.x;
    float m = -CUDART_INF_F, u = 0.0f, w = 0.0f;
    for (int c = 0; c < NCH; ++c) {
        const int idx = chain * NCH + c;
        if (d == 0) { g_PreM[idx] = m; g_PreU[idx] = u; }
        g_PreW[idx * DD + d] = w;
        float mb = g_AggM[idx], ub = g_AggU[idx], wb = g_AggW[idx * DD + d];
        float mn = fmaxf(m, mb);
        float ea = __expf(m - mn);
        float eb = __expf(mb - mn);
        u = u * ea + ub * eb;
        w = w * ea + wb * eb;
        m = mn;
    }
}

// ---------------- pass C: re-scan with prefix, emit h = w/u, head-sum via atomics ----------------
__global__ __launch_bounds__(64) void passC_kernel(float* __restrict__ out)
{
    const int chain = blockIdx.y;
    const int chunk = blockIdx.x;
    const int d     = threadIdx.x;
    const int b = chain >> 4, h = chain & 15;

    const int idx = chain * NCH + chunk;
    float m = g_PreM[idx];
    float u = g_PreU[idx];
    float w = g_PreW[idx * DD + d];

    const int t0 = chunk * TC;
#pragma unroll 4
    for (int t = t0; t < t0 + TC; ++t) {
        const size_t row = (size_t)b * TT + t;
        float s = g_ST[row * HH + h];
        float v = g_V[row * HD + h * DD + d];
        scan_step(m, u, w, s, v);
        atomicAdd(out + row * DD + d, w / u);
    }
}

// ---------------- launch ----------------
extern "C" void kernel_launch(void* const* d_in, const int* in_sizes, int n_in,
                              void* d_out, int out_size)
{
    const float* inputs = (const float*)d_in[0];   // [4,4096,1024]
    const float* kvk    = (const float*)d_in[1];   // [1024,16,64,2] == [1024,2048]
    const float* qk     = (const float*)d_in[2];   // [16,64]
    float* out = (float*)d_out;                    // [4,4096,64]

    zero_kernel<<<(out_size + 255) / 256, 256>>>(out, out_size);

    dim3 ggrid(NN / Bb_N, MM / Bb_M);              // (32, 128)
    gemm_relu_kernel<<<ggrid, 256>>>(inputs, kvk);

    // one warp per (row, head): MM*HH warps
    const int st_threads = MM * HH * 32;
    st_kernel<<<st_threads / 256, 256>>>(qk);

    dim3 sgrid(NCH, BB * HH);                      // (32, 64)
    passA_kernel<<<sgrid, 64>>>();
    passB_kernel<<<BB * HH, 64>>>();
    passC_kernel<<<sgrid, 64>>>(out);
}

// round 6
// speedup vs baseline: 2.5308x; 2.5308x over previous
#include <cuda_runtime.h>
#include <math_constants.h>
#include <cstdint>

// Problem constants
#define BB   4
#define TT   4096
#define DIN  1024
#define HH   16
#define DD   64
#define MM   (BB*TT)      // 16384 rows
#define NN   (HH*DD*2)    // 2048 gemm cols
#define HD   (HH*DD)      // 1024

// scan chunking
#define NCH  32
#define TC   (TT/NCH)     // 128

// GEMM tiling (tensor-core tf32) -- static smem < 48KB, no opt-in needed
#define BM 128
#define BN 128
#define BK 16
#define GTHREADS 256
#define AS_STRIDE 20      // BK + 4 pad
#define BS_STRIDE 136     // BN + 8 pad
#define AS_SIZE (BM*AS_STRIDE)   // 2560 floats
#define BS_SIZE (BK*BS_STRIDE)   // 2176 floats

// ---------------- scratch (device globals; no allocation allowed) ----------------
__device__ float g_Atf[(size_t)MM * DIN];  // 64 MB  tf32-rounded inputs
__device__ float g_Wtf[(size_t)DIN * NN];  // 8 MB   tf32-rounded kv_kernel
__device__ float g_K[(size_t)MM * HD];     // 64 MB
__device__ float g_V[(size_t)MM * HD];     // 64 MB
__device__ float g_ST[(size_t)MM * HH];    // 1 MB
__device__ float g_AggM[BB*HH*NCH];
__device__ float g_AggU[BB*HH*NCH];
__device__ float g_AggW[BB*HH*NCH*DD];
__device__ float g_PreM[BB*HH*NCH];
__device__ float g_PreU[BB*HH*NCH];
__device__ float g_PreW[BB*HH*NCH*DD];

// ---------------- helpers ----------------
__device__ __forceinline__ float tf32_rna(float x) {
    uint32_t u;
    asm("cvt.rna.tf32.f32 %0, %1;" : "=r"(u) : "f"(x));
    return __uint_as_float(u);
}

__device__ __forceinline__ void cp_async16(uint32_t saddr, const void* gptr) {
    asm volatile("cp.async.ca.shared.global [%0], [%1], 16;\n" :: "r"(saddr), "l"(gptr));
}
#define CP_COMMIT() asm volatile("cp.async.commit_group;\n")

// ---------------- zero output ----------------
__global__ void zero_kernel(float* __restrict__ out, int n) {
    int i = blockIdx.x * blockDim.x + threadIdx.x;
    if (i < n) out[i] = 0.0f;
}

// ---------------- tf32 RNA preprocessing ----------------
// NOTE: destination device globals are referenced from DEVICE code only.
// Passing __device__ symbols as host-side kernel arguments was the round-4/5 bug.
__global__ __launch_bounds__(256) void round_tf32_A(const float* __restrict__ in)
{
    int i = blockIdx.x * blockDim.x + threadIdx.x;   // grid sized exactly
    float4 v = ((const float4*)in)[i];
    v.x = tf32_rna(v.x); v.y = tf32_rna(v.y);
    v.z = tf32_rna(v.z); v.w = tf32_rna(v.w);
    ((float4*)g_Atf)[i] = v;
}

__global__ __launch_bounds__(256) void round_tf32_W(const float* __restrict__ in)
{
    int i = blockIdx.x * blockDim.x + threadIdx.x;
    float4 v = ((const float4*)in)[i];
    v.x = tf32_rna(v.x); v.y = tf32_rna(v.y);
    v.z = tf32_rna(v.z); v.w = tf32_rna(v.w);
    ((float4*)g_Wtf)[i] = v;
}

// ---------------- tensor-core GEMM: kv = relu(A @ W), deinterleave K/V ----------------
__global__ __launch_bounds__(GTHREADS) void gemm_tc_kernel()
{
    __shared__ __align__(16) float As[2][AS_SIZE];
    __shared__ __align__(16) float Bs[2][BS_SIZE];

    const int tid  = threadIdx.x;
    const int wid  = tid >> 5;
    const int lane = tid & 31;
    const int g    = lane >> 2;      // groupID 0..7
    const int tg   = lane & 3;       // tid-in-group 0..3
    const int wm   = wid & 1;        // warp M index (0..1) -> 64 rows each
    const int wn   = wid >> 1;       // warp N index (0..3) -> 32 cols each
    const int m0   = blockIdx.y * BM;
    const int n0   = blockIdx.x * BN;

    const float* Ab = g_Atf + (size_t)m0 * DIN;
    const float* Wb = g_Wtf + n0;

    // per-thread load coordinates (256 threads)
    const int ar0 = tid >> 2;            // A rows 0..63 (first f4) and +64
    const int akq = (tid & 3) * 4;       // k offset 0,4,8,12
    const int brw = tid >> 5;            // B rows 0..7 (first f4) and +8
    const int bcq = (tid & 31) * 4;      // B col offset 0..124

    float acc[4][4][4];
#pragma unroll
    for (int i = 0; i < 4; ++i)
#pragma unroll
        for (int j = 0; j < 4; ++j)
#pragma unroll
            for (int r = 0; r < 4; ++r) acc[i][j][r] = 0.0f;

    auto load_stage = [&](int s, int k0) {
        uint32_t abase = (uint32_t)__cvta_generic_to_shared(&As[s][0]);
        uint32_t bbase = (uint32_t)__cvta_generic_to_shared(&Bs[s][0]);
        cp_async16(abase + (ar0 * AS_STRIDE + akq) * 4,
                   Ab + (size_t)ar0 * DIN + k0 + akq);
        cp_async16(abase + ((ar0 + 64) * AS_STRIDE + akq) * 4,
                   Ab + (size_t)(ar0 + 64) * DIN + k0 + akq);
        cp_async16(bbase + (brw * BS_STRIDE + bcq) * 4,
                   Wb + (size_t)(k0 + brw) * NN + bcq);
        cp_async16(bbase + ((brw + 8) * BS_STRIDE + bcq) * 4,
                   Wb + (size_t)(k0 + brw + 8) * NN + bcq);
    };

    load_stage(0, 0);
    CP_COMMIT();

    const int NIT = DIN / BK;   // 64
#pragma unroll 1
    for (int it = 0; it < NIT; ++it) {
        const int s = it & 1;
        if (it + 1 < NIT) {
            load_stage(s ^ 1, (it + 1) * BK);
            CP_COMMIT();
            asm volatile("cp.async.wait_group 1;\n");
        } else {
            asm volatile("cp.async.wait_group 0;\n");
        }
        __syncthreads();

#pragma unroll
        for (int kc = 0; kc < 2; ++kc) {
            uint32_t a[4][4], b[4][2];
#pragma unroll
            for (int i = 0; i < 4; ++i) {
                const int r0 = wm * 64 + i * 16 + g;
                a[i][0] = __float_as_uint(As[s][r0 * AS_STRIDE + kc * 8 + tg]);
                a[i][1] = __float_as_uint(As[s][(r0 + 8) * AS_STRIDE + kc * 8 + tg]);
                a[i][2] = __float_as_uint(As[s][r0 * AS_STRIDE + kc * 8 + tg + 4]);
                a[i][3] = __float_as_uint(As[s][(r0 + 8) * AS_STRIDE + kc * 8 + tg + 4]);
            }
#pragma unroll
            for (int j = 0; j < 4; ++j) {
                const int c0 = wn * 32 + j * 8 + g;
                b[j][0] = __float_as_uint(Bs[s][(kc * 8 + tg) * BS_STRIDE + c0]);
                b[j][1] = __float_as_uint(Bs[s][(kc * 8 + tg + 4) * BS_STRIDE + c0]);
            }
#pragma unroll
            for (int i = 0; i < 4; ++i)
#pragma unroll
                for (int j = 0; j < 4; ++j)
                    asm volatile(
                        "mma.sync.aligned.m16n8k8.row.col.f32.tf32.tf32.f32 "
                        "{%0,%1,%2,%3}, {%4,%5,%6,%7}, {%8,%9}, {%0,%1,%2,%3};"
                        : "+f"(acc[i][j][0]), "+f"(acc[i][j][1]),
                          "+f"(acc[i][j][2]), "+f"(acc[i][j][3])
                        : "r"(a[i][0]), "r"(a[i][1]), "r"(a[i][2]), "r"(a[i][3]),
                          "r"(b[j][0]), "r"(b[j][1]));
        }
        __syncthreads();
    }

    // epilogue: relu + deinterleave into K/V
#pragma unroll
    for (int i = 0; i < 4; ++i) {
        const int r0 = m0 + wm * 64 + i * 16 + g;
#pragma unroll
        for (int j = 0; j < 4; ++j) {
            const int cn = n0 + wn * 32 + j * 8 + tg * 2;  // even gemm col
            const int c  = cn >> 1;                        // K/V col
            g_K[(size_t)r0 * HD + c]       = fmaxf(acc[i][j][0], 0.0f);
            g_V[(size_t)r0 * HD + c]       = fmaxf(acc[i][j][1], 0.0f);
            g_K[(size_t)(r0 + 8) * HD + c] = fmaxf(acc[i][j][2], 0.0f);
            g_V[(size_t)(r0 + 8) * HD + c] = fmaxf(acc[i][j][3], 0.0f);
        }
    }
}

// ---------------- st[b,t,h] = sum_d q[h,d] * K[row, h*64+d] ----------------
__global__ __launch_bounds__(256) void st_kernel(const float* __restrict__ q)
{
    const int gwarp = (blockIdx.x * blockDim.x + threadIdx.x) >> 5;
    const int lane  = threadIdx.x & 31;
    if (gwarp >= MM * HH) return;
    const int m = gwarp >> 4;      // row
    const int h = gwarp & 15;
    const float* krow = g_K + (size_t)m * HD + h * DD;
    const float* qrow = q + h * DD;
    float s = krow[lane] * qrow[lane] + krow[lane + 32] * qrow[lane + 32];
#pragma unroll
    for (int off = 16; off > 0; off >>= 1)
        s += __shfl_xor_sync(0xffffffffu, s, off);
    if (lane == 0) g_ST[(size_t)m * HH + h] = s;
}

// ---------------- scan combine step ----------------
__device__ __forceinline__ void scan_step(float& m, float& u, float& w, float s, float v)
{
    float mn = fmaxf(m, s);
    float sc = __expf(m - mn);   // exp(-inf) = 0 handles identity state
    float e  = __expf(s - mn);
    u = u * sc + e;
    w = w * sc + e * v;
    m = mn;
}

// ---------------- pass A: per-chunk aggregates ----------------
__global__ __launch_bounds__(64) void passA_kernel()
{
    const int chain = blockIdx.y;          // b*H + h
    const int chunk = blockIdx.x;
    const int d     = threadIdx.x;
    const int b = chain >> 4, h = chain & 15;

    float m = -CUDART_INF_F, u = 0.0f, w = 0.0f;
    const int t0 = chunk * TC;
#pragma unroll 4
    for (int t = t0; t < t0 + TC; ++t) {
        const size_t row = (size_t)b * TT + t;
        float s = g_ST[row * HH + h];
        float v = g_V[row * HD + h * DD + d];
        scan_step(m, u, w, s, v);
    }
    const int idx = chain * NCH + chunk;
    if (d == 0) { g_AggM[idx] = m; g_AggU[idx] = u; }
    g_AggW[idx * DD + d] = w;
}

// ---------------- pass B: exclusive prefix over chunks (serial, tiny) ----------------
__global__ __launch_bounds__(64) void passB_kernel()
{
    const int chain = blockIdx.x;
    const int d     = threadIdx.x;
    float m = -CUDART_INF_F, u = 0.0f, w = 0.0f;
    for (int c = 0; c < NCH; ++c) {
        const int idx = chain * NCH + c;
        if (d == 0) { g_PreM[idx] = m; g_PreU[idx] = u; }
        g_PreW[idx * DD + d] = w;
        float mb = g_AggM[idx], ub = g_AggU[idx], wb = g_AggW[idx * DD + d];
        float mn = fmaxf(m, mb);
        float ea = __expf(m - mn);
        float eb = __expf(mb - mn);
        u = u * ea + ub * eb;
        w = w * ea + wb * eb;
        m = mn;
    }
}

// ---------------- pass C: re-scan with prefix, emit h = w/u, head-sum via atomics ----------------
__global__ __launch_bounds__(64) void passC_kernel(float* __restrict__ out)
{
    const int chain = blockIdx.y;
    const int chunk = blockIdx.x;
    const int d     = threadIdx.x;
    const int b = chain >> 4, h = chain & 15;

    const int idx = chain * NCH + chunk;
    float m = g_PreM[idx];
    float u = g_PreU[idx];
    float w = g_PreW[idx * DD + d];

    const int t0 = chunk * TC;
#pragma unroll 4
    for (int t = t0; t < t0 + TC; ++t) {
        const size_t row = (size_t)b * TT + t;
        float s = g_ST[row * HH + h];
        float v = g_V[row * HD + h * DD + d];
        scan_step(m, u, w, s, v);
        atomicAdd(out + row * DD + d, w / u);
    }
}

// ---------------- launch ----------------
extern "C" void kernel_launch(void* const* d_in, const int* in_sizes, int n_in,
                              void* d_out, int out_size)
{
    const float* inputs = (const float*)d_in[0];   // [4,4096,1024]
    const float* kvk    = (const float*)d_in[1];   // [1024,16,64,2] == [1024,2048]
    const float* qk     = (const float*)d_in[2];   // [16,64]
    float* out = (float*)d_out;                    // [4,4096,64]

    zero_kernel<<<(out_size + 255) / 256, 256>>>(out, out_size);

    // tf32 round-to-nearest preprocessing (device globals referenced device-side)
    {
        const int nA4 = (MM * DIN) / 4;   // 4,194,304  -> 16384 blocks
        const int nW4 = (DIN * NN) / 4;   // 524,288    -> 2048 blocks
        round_tf32_A<<<nA4 / 256, 256>>>(inputs);
        round_tf32_W<<<nW4 / 256, 256>>>(kvk);
    }

    dim3 ggrid(NN / BN, MM / BM);                  // (16, 128)
    gemm_tc_kernel<<<ggrid, GTHREADS>>>();

    // one warp per (row, head): MM*HH warps
    const int st_threads = MM * HH * 32;
    st_kernel<<<st_threads / 256, 256>>>(qk);

    dim3 sgrid(NCH, BB * HH);                      // (32, 64)
    passA_kernel<<<sgrid, 64>>>();
    passB_kernel<<<BB * HH, 64>>>();
    passC_kernel<<<sgrid, 64>>>(out);
}

// round 10
// speedup vs baseline: 2.9359x; 1.1601x over previous
#include <cuda_runtime.h>
#include <math_constants.h>
#include <cstdint>

// Problem constants
#define BB   4
#define TT   4096
#define DIN  1024
#define HH   16
#define DD   64
#define MM   (BB*TT)      // 16384
#define NN   (HH*DD*2)    // 2048
#define HD   (HH*DD)      // 1024

// scan chunking
#define NCH  32
#define TC   (TT/NCH)     // 128

// GEMM tiling: CTA 128x128, 4 warps (2x2), warp tile 64x64, ldmatrix operands
#define Bb_M 128
#define Bb_N 128
#define BB_K 16
#define GT   128
#define TS   20                      // smem row stride (16 + 4 pad), floats
#define TILE_FLOATS (128*TS)         // 2560 floats per tile buffer

// ---------------- scratch (device globals; referenced from device code ONLY) ----------------
__device__ float g_Atf[(size_t)MM * DIN];  // 64 MB tf32-RNA inputs
__device__ float g_Wt [(size_t)NN * DIN];  // 8 MB  tf32-RNA weights, transposed [N,K]
__device__ float g_K[(size_t)MM * HD];     // 64 MB
__device__ float g_V[(size_t)MM * HD];     // 64 MB
__device__ float g_ST[(size_t)MM * HH];    // 1 MB
__device__ float g_AggM[BB*HH*NCH];
__device__ float g_AggU[BB*HH*NCH];
__device__ float g_AggW[BB*HH*NCH*DD];
__device__ float g_PreM[BB*HH*NCH];
__device__ float g_PreU[BB*HH*NCH];
__device__ float g_PreW[BB*HH*NCH*DD];

// ---------------- helpers ----------------
__device__ __forceinline__ float tf32_rna(float x) {
    uint32_t u;
    asm("cvt.rna.tf32.f32 %0, %1;" : "=r"(u) : "f"(x));
    return __uint_as_float(u);
}
__device__ __forceinline__ void cp_async16(uint32_t saddr, const void* gptr) {
    asm volatile("cp.async.ca.shared.global [%0], [%1], 16;\n" :: "r"(saddr), "l"(gptr));
}
#define CP_COMMIT() asm volatile("cp.async.commit_group;\n")

__device__ __forceinline__ void ldsm_x4(uint32_t* r, uint32_t addr) {
    asm volatile("ldmatrix.sync.aligned.m8n8.x4.shared.b16 {%0,%1,%2,%3}, [%4];"
                 : "=r"(r[0]), "=r"(r[1]), "=r"(r[2]), "=r"(r[3]) : "r"(addr));
}

// ---------------- zero output ----------------
__global__ void zero_kernel(float* __restrict__ out, int n) {
    int i = blockIdx.x * blockDim.x + threadIdx.x;
    if (i < n) out[i] = 0.0f;
}

// ---------------- tf32 RNA preprocessing ----------------
__global__ __launch_bounds__(256) void round_tf32_A(const float* __restrict__ in)
{
    int i = blockIdx.x * blockDim.x + threadIdx.x;
    float4 v = ((const float4*)in)[i];
    v.x = tf32_rna(v.x); v.y = tf32_rna(v.y);
    v.z = tf32_rna(v.z); v.w = tf32_rna(v.w);
    ((float4*)g_Atf)[i] = v;
}

// transpose + RNA-round W [DIN, NN] -> g_Wt [NN, DIN]
__global__ __launch_bounds__(256) void transW_kernel(const float* __restrict__ W)
{
    __shared__ float t[32][33];
    const int n0 = blockIdx.x * 32;
    const int k0 = blockIdx.y * 32;
    const int tx = threadIdx.x & 31;
    const int ty = threadIdx.x >> 5;   // 0..7
#pragma unroll
    for (int i = 0; i < 4; ++i)
        t[ty + i * 8][tx] = tf32_rna(W[(size_t)(k0 + ty + i * 8) * NN + n0 + tx]);
    __syncthreads();
#pragma unroll
    for (int i = 0; i < 4; ++i)
        g_Wt[(size_t)(n0 + ty + i * 8) * DIN + k0 + tx] = t[tx][ty + i * 8];
}

// ---------------- tensor GEMM (mma.sync tf32 + ldmatrix): kv = relu(A @ W^T_t) ----------------
__global__ __launch_bounds__(GT) void gemm_tc_kernel()
{
    __shared__ __align__(16) float As[2][TILE_FLOATS];
    __shared__ __align__(16) float Bs[2][TILE_FLOATS];

    const int tid  = threadIdx.x;
    const int wid  = tid >> 5;
    const int lane = tid & 31;
    const int g    = lane >> 2;      // 0..7
    const int tg   = lane & 3;       // 0..3
    const int wm   = wid & 1;        // warp M (0..1) -> 64 rows
    const int wn   = wid >> 1;       // warp N (0..1) -> 64 cols
    const int m0   = blockIdx.y * Bb_M;
    const int n0   = blockIdx.x * Bb_N;

    const float* Ab = g_Atf + (size_t)m0 * DIN;
    const float* Bb = g_Wt  + (size_t)n0 * DIN;

    // cp.async mapping: 4 threads per row, 32 rows per pass, 4 passes
    const int lrow = tid >> 2;           // 0..31
    const int lcol = (tid & 3) * 4;      // 0,4,8,12

    // ldmatrix per-lane offsets
    const int a_row = (lane & 7) + ((lane & 8)  ? 8 : 0);
    const int a_col = (lane & 16) ? 4 : 0;
    const int b_row = (lane & 7) + ((lane & 16) ? 8 : 0);
    const int b_col = (lane & 8)  ? 4 : 0;
    const uint32_t as_base = (uint32_t)__cvta_generic_to_shared(&As[0][0]);
    const uint32_t bs_base = (uint32_t)__cvta_generic_to_shared(&Bs[0][0]);
    // float offsets within a tile
    const int a_off = (wm * 64 + a_row) * TS + a_col;
    const int b_off = (wn * 64 + b_row) * TS + b_col;

    float acc[4][8][4];
#pragma unroll
    for (int i = 0; i < 4; ++i)
#pragma unroll
        for (int j = 0; j < 8; ++j)
#pragma unroll
            for (int r = 0; r < 4; ++r) acc[i][j][r] = 0.0f;

    auto load_stage = [&](int s, int k0) {
        uint32_t ab = (uint32_t)__cvta_generic_to_shared(&As[s][0]);
        uint32_t bb = (uint32_t)__cvta_generic_to_shared(&Bs[s][0]);
#pragma unroll
        for (int p = 0; p < 4; ++p) {
            const int r = lrow + p * 32;
            cp_async16(ab + (r * TS + lcol) * 4, Ab + (size_t)r * DIN + k0 + lcol);
            cp_async16(bb + (r * TS + lcol) * 4, Bb + (size_t)r * DIN + k0 + lcol);
        }
        CP_COMMIT();
    };

    load_stage(0, 0);

    const int NIT = DIN / BB_K;   // 64
#pragma unroll 1
    for (int it = 0; it < NIT; ++it) {
        const int s = it & 1;
        if (it + 1 < NIT) {
            load_stage(s ^ 1, (it + 1) * BB_K);
            asm volatile("cp.async.wait_group 1;\n");
        } else {
            asm volatile("cp.async.wait_group 0;\n");
        }
        __syncthreads();

        const uint32_t abase = as_base + (uint32_t)(s * TILE_FLOATS + a_off) * 4;
        const uint32_t bbase = bs_base + (uint32_t)(s * TILE_FLOATS + b_off) * 4;

#pragma unroll
        for (int kc = 0; kc < 2; ++kc) {
            uint32_t a[4][4], b[4][4];
#pragma unroll
            for (int i = 0; i < 4; ++i)
                ldsm_x4(a[i], abase + (uint32_t)(i * 16 * TS + kc * 8) * 4);
#pragma unroll
            for (int j2 = 0; j2 < 4; ++j2)
                ldsm_x4(b[j2], bbase + (uint32_t)(j2 * 16 * TS + kc * 8) * 4);
#pragma unroll
            for (int i = 0; i < 4; ++i)
#pragma unroll
                for (int j = 0; j < 8; ++j)
                    asm volatile(
                        "mma.sync.aligned.m16n8k8.row.col.f32.tf32.tf32.f32 "
                        "{%0,%1,%2,%3}, {%4,%5,%6,%7}, {%8,%9}, {%0,%1,%2,%3};"
                        : "+f"(acc[i][j][0]), "+f"(acc[i][j][1]),
                          "+f"(acc[i][j][2]), "+f"(acc[i][j][3])
                        : "r"(a[i][0]), "r"(a[i][1]), "r"(a[i][2]), "r"(a[i][3]),
                          "r"(b[j >> 1][2 * (j & 1)]), "r"(b[j >> 1][2 * (j & 1) + 1]));
        }
        __syncthreads();
    }

    // epilogue: relu + deinterleave into K/V
    // frag (i,j): rows r0 = m0+wm*64+i*16+g (and +8); even col cn = n0+wn*64+j*8+2tg
    // K col c = (n0>>1) + wn*32 + j*4 + tg; acc[0]/[1] -> K/V row r0; acc[2]/[3] -> row r0+8
    const int cb = (n0 >> 1) + wn * 32 + tg;
#pragma unroll
    for (int i = 0; i < 4; ++i) {
        const size_t r0 = (size_t)(m0 + wm * 64 + i * 16 + g);
        const size_t r1 = r0 + 8;
#pragma unroll
        for (int j = 0; j < 8; ++j) {
            const int c = cb + j * 4;
            g_K[r0 * HD + c] = fmaxf(acc[i][j][0], 0.0f);
            g_V[r0 * HD + c] = fmaxf(acc[i][j][1], 0.0f);
            g_K[r1 * HD + c] = fmaxf(acc[i][j][2], 0.0f);
            g_V[r1 * HD + c] = fmaxf(acc[i][j][3], 0.0f);
        }
    }
}

// ---------------- st[b,t,h] = sum_d q[h,d] * K[row, h*64+d] ----------------
__global__ __launch_bounds__(256) void st_kernel(const float* __restrict__ q)
{
    const int gwarp = (blockIdx.x * blockDim.x + threadIdx.x) >> 5;
    const int lane  = threadIdx.x & 31;
    if (gwarp >= MM * HH) return;
    const int m = gwarp >> 4;
    const int h = gwarp & 15;
    const float* krow = g_K + (size_t)m * HD + h * DD;
    const float* qrow = q + h * DD;
    float s = krow[lane] * qrow[lane] + krow[lane + 32] * qrow[lane + 32];
#pragma unroll
    for (int off = 16; off > 0; off >>= 1)
        s += __shfl_xor_sync(0xffffffffu, s, off);
    if (lane == 0) g_ST[(size_t)m * HH + h] = s;
}

// ---------------- scan combine step ----------------
__device__ __forceinline__ void scan_step(float& m, float& u, float& w, float s, float v)
{
    float mn = fmaxf(m, s);
    float sc = __expf(m - mn);
    float e  = __expf(s - mn);
    u = u * sc + e;
    w = w * sc + e * v;
    m = mn;
}

// ---------------- pass A: per-chunk aggregates ----------------
__global__ __launch_bounds__(64) void passA_kernel()
{
    const int chain = blockIdx.y;
    const int chunk = blockIdx.x;
    const int d     = threadIdx.x;
    const int b = chain >> 4, h = chain & 15;

    float m = -CUDART_INF_F, u = 0.0f, w = 0.0f;
    const int t0 = chunk * TC;
#pragma unroll 4
    for (int t = t0; t < t0 + TC; ++t) {
        const size_t row = (size_t)b * TT + t;
        float s = g_ST[row * HH + h];
        float v = g_V[row * HD + h * DD + d];
        scan_step(m, u, w, s, v);
    }
    const int idx = chain * NCH + chunk;
    if (d == 0) { g_AggM[idx] = m; g_AggU[idx] = u; }
    g_AggW[idx * DD + d] = w;
}

// ---------------- pass B: exclusive prefix over chunks ----------------
__global__ __launch_bounds__(64) void passB_kernel()
{
    const int chain = blockIdx.x;
    const int d     = threadIdx.x;
    float m = -CUDART_INF_F, u = 0.0f, w = 0.0f;
    for (int c = 0; c < NCH; ++c) {
        const int idx = chain * NCH + c;
        if (d == 0) { g_PreM[idx] = m; g_PreU[idx] = u; }
        g_PreW[idx * DD + d] = w;
        float mb = g_AggM[idx], ub = g_AggU[idx], wb = g_AggW[idx * DD + d];
        float mn = fmaxf(m, mb);
        float ea = __expf(m - mn);
        float eb = __expf(mb - mn);
        u = u * ea + ub * eb;
        w = w * ea + wb * eb;
        m = mn;
    }
}

// ---------------- pass C: re-scan with prefix, head-sum via atomics ----------------
__global__ __launch_bounds__(64) void passC_kernel(float* __restrict__ out)
{
    const int chain = blockIdx.y;
    const int chunk = blockIdx.x;
    const int d     = threadIdx.x;
    const int b = chain >> 4, h = chain & 15;

    const int idx = chain * NCH + chunk;
    float m = g_PreM[idx];
    float u = g_PreU[idx];
    float w = g_PreW[idx * DD + d];

    const int t0 = chunk * TC;
#pragma unroll 4
    for (int t = t0; t < t0 + TC; ++t) {
        const size_t row = (size_t)b * TT + t;
        float s = g_ST[row * HH + h];
        float v = g_V[row * HD + h * DD + d];
        scan_step(m, u, w, s, v);
        atomicAdd(out + row * DD + d, w / u);
    }
}

// ---------------- launch ----------------
extern "C" void kernel_launch(void* const* d_in, const int* in_sizes, int n_in,
                              void* d_out, int out_size)
{
    const float* inputs = (const float*)d_in[0];   // [4,4096,1024]
    const float* kvk    = (const float*)d_in[1];   // [1024,2048]
    const float* qk     = (const float*)d_in[2];   // [16,64]
    float* out = (float*)d_out;                    // [4,4096,64]

    zero_kernel<<<(out_size + 255) / 256, 256>>>(out, out_size);

    round_tf32_A<<<(MM * DIN / 4) / 256, 256>>>(inputs);
    {
        dim3 tg(NN / 32, DIN / 32);                // (64, 32)
        transW_kernel<<<tg, 256>>>(kvk);
    }

    dim3 ggrid(NN / Bb_N, MM / Bb_M);              // (16, 128)
    gemm_tc_kernel<<<ggrid, GT>>>();

    const int st_threads = MM * HH * 32;
    st_kernel<<<st_threads / 256, 256>>>(qk);

    dim3 sgrid(NCH, BB * HH);                      // (32, 64)
    passA_kernel<<<sgrid, 64>>>();
    passB_kernel<<<BB * HH, 64>>>();
    passC_kernel<<<sgrid, 64>>>(out);
}